// round 17
// baseline (speedup 1.0000x reference)
#include <cuda_runtime.h>
#include <cuda_bf16.h>
#include <math.h>
#include <stdint.h>

// Problem shape (fixed by the reference setup_inputs)
#define BB 8192
#define MM_ 3129
#define MPAD 3584        // M padded to 14 tiles of 256
#define DD 512
#define NGROUP 2         // m-groups (grid.y)
#define MT_PER_G 7       // 256-wide m-tiles per group (2*7*256 = 3584)
#define NTW 256          // m-cols per CTA tile

// -------- device scratch (no allocations allowed) --------
__device__ __nv_bfloat16 g_abf[MPAD * DD];   // normalized ans_embedding, bf16, zero-padded rows
__device__ __nv_bfloat16 g_gbf[BB * DD];     // normalized mm_proj, bf16
__device__ float g_part_sum[NGROUP * BB];
__device__ float g_part_pos[NGROUP * BB];
__device__ float g_row_ce_rubi[BB];
__device__ float g_row_ce_q[BB];
__device__ float g_row_obj[BB];
__device__ int   g_cid[BB];
__device__ float g_red4[64 * 4];             // stage-1 partials of final reduce

// ---------------- class_id dtype sniff + canonicalize ----------------
__global__ void cid_convert_kernel(const int* __restrict__ raw) {
    __shared__ int is64;
    if (threadIdx.x == 0) {
        int acc = 0;
#pragma unroll
        for (int i = 0; i < 64; i++) acc |= raw[2 * i + 1];
        is64 = (acc == 0);
    }
    __syncthreads();
    int i = blockIdx.x * blockDim.x + threadIdx.x;
    if (i < BB) {
        int v = is64 ? raw[2 * i] : raw[i];
        g_cid[i] = min(max(v, 0), MM_ - 1);
    }
}

// ---------------- row L2-normalize -> bf16 ----------------
__device__ __forceinline__ void normalize_row_bf16(const float* __restrict__ in,
                                                   __nv_bfloat16* __restrict__ out,
                                                   int row, int nrows) {
    __nv_bfloat16* o = out + (size_t)row * DD;
    if (row >= nrows) {  // pad rows: zeros
        for (int k = threadIdx.x; k < DD; k += blockDim.x) o[k] = __float2bfloat16(0.f);
        return;
    }
    const float* x = in + (size_t)row * DD;
    float s = 0.f;
    for (int k = threadIdx.x; k < DD; k += blockDim.x) {
        float v = x[k];
        s += v * v;
    }
    __shared__ float red[4];
    for (int off = 16; off > 0; off >>= 1) s += __shfl_xor_sync(0xffffffffu, s, off);
    if ((threadIdx.x & 31) == 0) red[threadIdx.x >> 5] = s;
    __syncthreads();
    if (threadIdx.x == 0) {
        float t = red[0] + red[1] + red[2] + red[3];
        red[0] = 1.0f / fmaxf(sqrtf(t), 1e-8f);
    }
    __syncthreads();
    float inv = red[0];
    for (int k = threadIdx.x; k < DD; k += blockDim.x)
        o[k] = __float2bfloat16(x[k] * inv);
}

__global__ void normalize_ans_kernel(const float* __restrict__ in) {
    normalize_row_bf16(in, g_abf, blockIdx.x, MM_);
}
__global__ void normalize_g_kernel(const float* __restrict__ in) {
    normalize_row_bf16(in, g_gbf, blockIdx.x, BB);
}

// ---------------- PTX helpers ----------------
__device__ __forceinline__ void cp_async16(uint32_t saddr, const void* gaddr) {
    asm volatile("cp.async.ca.shared.global [%0], [%1], 16;\n" :: "r"(saddr), "l"(gaddr) : "memory");
}
__device__ __forceinline__ void cp_commit() {
    asm volatile("cp.async.commit_group;\n" ::: "memory");
}
template <int N>
__device__ __forceinline__ void cp_wait_group() {
    asm volatile("cp.async.wait_group %0;\n" :: "n"(N) : "memory");
}
__device__ __forceinline__ void ldmatrix_x4(uint32_t* r, uint32_t addr) {
    asm volatile("ldmatrix.sync.aligned.m8n8.x4.shared.b16 {%0,%1,%2,%3}, [%4];\n"
                 : "=r"(r[0]), "=r"(r[1]), "=r"(r[2]), "=r"(r[3]) : "r"(addr));
}
__device__ __forceinline__ void mma_bf16(float* c, const uint32_t* a, uint32_t b0, uint32_t b1) {
    asm volatile("mma.sync.aligned.m16n8k16.row.col.f32.bf16.bf16.f32 "
                 "{%0,%1,%2,%3}, {%4,%5,%6,%7}, {%8,%9}, {%0,%1,%2,%3};\n"
                 : "+f"(c[0]), "+f"(c[1]), "+f"(c[2]), "+f"(c[3])
                 : "r"(a[0]), "r"(a[1]), "r"(a[2]), "r"(a[3]), "r"(b0), "r"(b1));
}

// ---------------- NCE tensor-core GEMM + streaming softmax ----------------
// CTA tile: 128 (b) x 256 (m), K=512 split into 8 chunks of 64.
// A resident in smem (133KB); B double-buffered 64-wide chunks (36.9KB each).
// 256 threads: 8 warps in 2(m) x 4(n); warp tile 64x64 -> LDSM bytes/MMA
// halved vs 32x32 (128 vs 256 B). 1 CTA/SM, grid (64, 2) = 128 CTAs = 1 wave.
#define BTILE 128
#define KCH 64                       // k-chunk width
#define A_STRIDE 520                 // bf16 elems (1040B rows: ldmatrix conflict-free)
#define B_STRIDE 72                  // bf16 elems (144B rows: conflict-free)
#define SMEM_A_BYTES (BTILE * A_STRIDE * 2)          // 133120
#define SMEM_B_BYTES (NTW * B_STRIDE * 2)            // 36864 per buffer
#define SMEM_RED_OFF (SMEM_A_BYTES + 2 * SMEM_B_BYTES)   // 206848
#define SMEM_TOTAL   (SMEM_RED_OFF + 4096)

extern __shared__ __align__(16) char dynsmem[];

__global__ void __launch_bounds__(256, 1) nce_mma_kernel() {
    const int tid = threadIdx.x;
    const int L   = tid & 31;
    const int w   = tid >> 5;
    const int wm  = w >> 2;           // 0..1 -> 64-row slice
    const int wn  = w & 3;            // 0..3 -> 64-col slice
    const int q   = L & 3;
    const int g   = L >> 2;
    const int b0  = blockIdx.x * BTILE;
    const int gy  = blockIdx.y;

    const uint32_t sA32 = (uint32_t)__cvta_generic_to_shared(dynsmem);
    const uint32_t sB32 = sA32 + SMEM_A_BYTES;
    float* redS = (float*)(dynsmem + SMEM_RED_OFF);           // [128][4]
    float* redP = redS + 512;

    // ---- A resident load (128 x 512 bf16) via cp.async ----
    {
        const __nv_bfloat16* gA = g_gbf + (size_t)b0 * DD;
#pragma unroll
        for (int l = 0; l < 32; l++) {
            int idx = tid + l * 256;         // over 128 rows x 64 uint4
            int row = idx >> 6, qq = idx & 63;
            uint32_t sa = sA32 + (uint32_t)(row * (A_STRIDE * 2) + qq * 16);
            cp_async16(sa, gA + (size_t)row * DD + qq * 8);
        }
        cp_commit();
    }

    // per-thread running softmax state: 8 rows (wm*64 + im*16 + g + h*8)
    float rs[8], ps[8];
    int cid8[8];
#pragma unroll
    for (int j = 0; j < 8; j++) {
        rs[j] = 0.f; ps[j] = 0.f;
        int row_local = wm * 64 + (j >> 1) * 16 + g + (j & 1) * 8;
        cid8[j] = g_cid[b0 + row_local];
    }

    for (int mt = 0; mt < MT_PER_G; mt++) {
        const int mbase = gy * (MT_PER_G * NTW) + mt * NTW;
        const __nv_bfloat16* gB = g_abf + (size_t)mbase * DD;

        // prologue: issue B chunk 0 into buffer 0 (256 rows x 8 uint4 = 2048 units)
#pragma unroll
        for (int l = 0; l < 8; l++) {
            int idx = tid + l * 256;
            int row = idx >> 3, qq = idx & 7;
            uint32_t sa = sB32 + (uint32_t)(row * (B_STRIDE * 2) + qq * 16);
            cp_async16(sa, gB + (size_t)row * DD + qq * 8);
        }
        cp_commit();

        float acc[4][8][4];
#pragma unroll
        for (int im = 0; im < 4; im++)
#pragma unroll
            for (int in = 0; in < 8; in++)
#pragma unroll
                for (int c = 0; c < 4; c++) acc[im][in][c] = 0.f;

        for (int kc = 0; kc < 8; kc++) {
            const int buf = kc & 1;
            cp_wait_group<0>();
            __syncthreads();
            if (kc < 7) {   // prefetch next chunk; overlaps with compute below
                int nb = buf ^ 1;
#pragma unroll
                for (int l = 0; l < 8; l++) {
                    int idx = tid + l * 256;
                    int row = idx >> 3, qq = idx & 7;
                    uint32_t sa = sB32 + (uint32_t)(nb * SMEM_B_BYTES + row * (B_STRIDE * 2) + qq * 16);
                    cp_async16(sa, gB + (size_t)row * DD + (kc + 1) * KCH + qq * 8);
                }
                cp_commit();
            }

            const uint32_t sBp = sB32 + (uint32_t)(buf * SMEM_B_BYTES);
#pragma unroll
            for (int ks = 0; ks < 4; ks++) {
                uint32_t a_regs[4][4];
#pragma unroll
                for (int im = 0; im < 4; im++) {
                    int row = wm * 64 + im * 16 + (L & 15);
                    int col = kc * KCH + ks * 16 + ((L >> 4) << 3);
                    ldmatrix_x4(a_regs[im], sA32 + (uint32_t)((row * A_STRIDE + col) * 2));
                }
                uint32_t b_regs[4][4];
#pragma unroll
                for (int ip = 0; ip < 4; ip++) {
                    int rown = wn * 64 + ip * 16 + (L & 7) + ((L >> 4) << 3);
                    int col  = ks * 16 + ((L >> 3) & 1) * 8;
                    ldmatrix_x4(b_regs[ip], sBp + (uint32_t)((rown * B_STRIDE + col) * 2));
                }
#pragma unroll
                for (int im = 0; im < 4; im++)
#pragma unroll
                    for (int in = 0; in < 8; in++) {
                        int ip = in >> 1, lo = (in & 1) * 2;
                        mma_bf16(acc[im][in], a_regs[im], b_regs[ip][lo], b_regs[ip][lo + 1]);
                    }
            }
        }

        // epilogue for this m-tile: exp-accumulate + positive pick (registers only)
#pragma unroll
        for (int im = 0; im < 4; im++) {
#pragma unroll
            for (int in = 0; in < 8; in++) {
                int m = mbase + wn * 64 + in * 8 + q * 2;
                const float* c = acc[im][in];
                if (m < MM_) {
                    rs[im * 2 + 0] += __expf(c[0]);
                    rs[im * 2 + 1] += __expf(c[2]);
                    if (m == cid8[im * 2 + 0]) ps[im * 2 + 0] += c[0];
                    if (m == cid8[im * 2 + 1]) ps[im * 2 + 1] += c[2];
                }
                if (m + 1 < MM_) {
                    rs[im * 2 + 0] += __expf(c[1]);
                    rs[im * 2 + 1] += __expf(c[3]);
                    if (m + 1 == cid8[im * 2 + 0]) ps[im * 2 + 0] += c[1];
                    if (m + 1 == cid8[im * 2 + 1]) ps[im * 2 + 1] += c[3];
                }
            }
        }
    }

    // reduce across the 4 lanes sharing each row (q dimension), deterministic
#pragma unroll
    for (int j = 0; j < 8; j++) {
        float s = rs[j], pp = ps[j];
        s  += __shfl_xor_sync(0xffffffffu, s, 1);
        s  += __shfl_xor_sync(0xffffffffu, s, 2);
        pp += __shfl_xor_sync(0xffffffffu, pp, 1);
        pp += __shfl_xor_sync(0xffffffffu, pp, 2);
        rs[j] = s; ps[j] = pp;
    }
    __syncthreads();
    if (q == 0) {
#pragma unroll
        for (int j = 0; j < 8; j++) {
            int row_local = wm * 64 + (j >> 1) * 16 + g + (j & 1) * 8;
            redS[row_local * 4 + wn] = rs[j];
            redP[row_local * 4 + wn] = ps[j];
        }
    }
    __syncthreads();
    if (tid < BTILE) {
        float s  = redS[tid * 4 + 0] + redS[tid * 4 + 1] + redS[tid * 4 + 2] + redS[tid * 4 + 3];
        float pp = redP[tid * 4 + 0] + redP[tid * 4 + 1] + redP[tid * 4 + 2] + redP[tid * 4 + 3];
        g_part_sum[gy * BB + b0 + tid] = s;
        g_part_pos[gy * BB + b0 + tid] = pp;
    }
}

// ---------------- CE (both logits) + object-cosine, one block per row ----------------
__global__ __launch_bounds__(256) void ce_obj_kernel(const float* __restrict__ logits_q,
                                                     const float* __restrict__ logits_rubi,
                                                     const float* __restrict__ v_max,
                                                     const float* __restrict__ mmv) {
    const int b = blockIdx.x;
    const int t = threadIdx.x;
    const float* rq = logits_q + (size_t)b * MM_;
    const float* rr = logits_rubi + (size_t)b * MM_;
    const float* v  = v_max + (size_t)b * DD;
    const float* qv = mmv + (size_t)b * DD;

    float sq = 0.f, sr = 0.f;
    for (int m = t; m < MM_; m += 256) {
        sq += __expf(rq[m]);
        sr += __expf(rr[m]);
    }
    float sv = 0.f, sm2 = 0.f, dt = 0.f;
    for (int k = t; k < DD; k += 256) {
        float a = v[k], c = qv[k];
        sv += a * a;
        sm2 += c * c;
        dt += a * c;
    }
    for (int o = 16; o > 0; o >>= 1) {
        sq  += __shfl_xor_sync(0xffffffffu, sq, o);
        sr  += __shfl_xor_sync(0xffffffffu, sr, o);
        sv  += __shfl_xor_sync(0xffffffffu, sv, o);
        sm2 += __shfl_xor_sync(0xffffffffu, sm2, o);
        dt  += __shfl_xor_sync(0xffffffffu, dt, o);
    }
    __shared__ float rsm[8][5];
    int wid = t >> 5;
    if ((t & 31) == 0) {
        rsm[wid][0] = sq; rsm[wid][1] = sr; rsm[wid][2] = sv; rsm[wid][3] = sm2; rsm[wid][4] = dt;
    }
    __syncthreads();
    if (t == 0) {
        float SQ = 0.f, SR = 0.f, SV = 0.f, SM = 0.f, DT = 0.f;
#pragma unroll
        for (int w = 0; w < 8; w++) {
            SQ += rsm[w][0]; SR += rsm[w][1]; SV += rsm[w][2]; SM += rsm[w][3]; DT += rsm[w][4];
        }
        int cid = g_cid[b];
        g_row_ce_q[b]    = logf(SQ) - rq[cid];
        g_row_ce_rubi[b] = logf(SR) - rr[cid];
        float cosv = DT / (fmaxf(sqrtf(SV), 1e-8f) * fmaxf(sqrtf(SM), 1e-8f));
        g_row_obj[b] = 1.0f - cosv;
    }
}

// ---------------- deterministic final reduction (2-stage) ----------------
__global__ __launch_bounds__(128) void reduce_stage1_kernel() {
    const int t = threadIdx.x;
    const int b = blockIdx.x * 128 + t;

    float se = 0.f, pp = 0.f;
#pragma unroll
    for (int gy = 0; gy < NGROUP; gy++) {
        se += g_part_sum[gy * BB + b];
        pp += g_part_pos[gy * BB + b];
    }
    float a_nce = logf(se) - pp;
    float a_obj = g_row_obj[b];
    float a_cr  = g_row_ce_rubi[b];
    float a_cq  = g_row_ce_q[b];

    for (int o = 16; o > 0; o >>= 1) {
        a_nce += __shfl_xor_sync(0xffffffffu, a_nce, o);
        a_obj += __shfl_xor_sync(0xffffffffu, a_obj, o);
        a_cr  += __shfl_xor_sync(0xffffffffu, a_cr, o);
        a_cq  += __shfl_xor_sync(0xffffffffu, a_cq, o);
    }
    __shared__ float sm[4][4];
    if ((t & 31) == 0) {
        int w = t >> 5;
        sm[w][0] = a_nce; sm[w][1] = a_obj; sm[w][2] = a_cr; sm[w][3] = a_cq;
    }
    __syncthreads();
    if (t < 4) {
        g_red4[blockIdx.x * 4 + t] = sm[0][t] + sm[1][t] + sm[2][t] + sm[3][t];
    }
}

__global__ __launch_bounds__(32) void reduce_stage2_kernel(float* __restrict__ out) {
    if (threadIdx.x == 0) {
        float nce = 0.f, obj = 0.f, cr = 0.f, cq = 0.f;
#pragma unroll
        for (int blk = 0; blk < 64; blk++) {
            nce += g_red4[blk * 4 + 0];
            obj += g_red4[blk * 4 + 1];
            cr  += g_red4[blk * 4 + 2];
            cq  += g_red4[blk * 4 + 3];
        }
        const float inv = 1.0f / (float)BB;
        nce *= inv; obj *= inv; cr *= inv; cq *= inv;
        float fusion = (cr + obj + nce) * (1.0f / 3.0f);
        float question = cq;
        out[0] = fusion + question;  // question_loss_weight = 1.0
        out[1] = fusion;
        out[2] = question;
    }
}

// ---------------- launcher ----------------
extern "C" void kernel_launch(void* const* d_in, const int* in_sizes, int n_in,
                              void* d_out, int out_size) {
    const float* mm_proj     = (const float*)d_in[0];
    const float* ans_emb     = (const float*)d_in[1];
    const float* v_max       = (const float*)d_in[2];
    const float* mmv         = (const float*)d_in[3];
    const float* logits_q    = (const float*)d_in[4];
    const float* logits_rubi = (const float*)d_in[5];
    const int*   class_raw   = (const int*)d_in[6];
    float* out = (float*)d_out;

    cudaFuncSetAttribute(nce_mma_kernel, cudaFuncAttributeMaxDynamicSharedMemorySize, SMEM_TOTAL);

    cid_convert_kernel<<<(BB + 255) / 256, 256>>>(class_raw);
    normalize_ans_kernel<<<MPAD, 128>>>(ans_emb);
    normalize_g_kernel<<<BB, 128>>>(mm_proj);
    dim3 grid(BB / BTILE, NGROUP);
    nce_mma_kernel<<<grid, 256, SMEM_TOTAL>>>();
    ce_obj_kernel<<<BB, 256>>>(logits_q, logits_rubi, v_max, mmv);
    reduce_stage1_kernel<<<64, 128>>>();
    reduce_stage2_kernel<<<1, 32>>>(out);
}